// round 16
// baseline (speedup 1.0000x reference)
#include <cuda_runtime.h>
#include <math.h>

#define VOCAB 50000
#define E 128
#define H 128
#define B 256
#define T 2048

typedef unsigned long long ull;

// Packed f32x2 FMA (Blackwell)
#define FMA2(d, a, b, c) \
    asm("fma.rn.f32x2 %0, %1, %2, %3;" : "=l"(d) : "l"(a), "l"(b), "l"(c))
#define PACK2(d, lo, hi) \
    asm("mov.b64 %0, {%1, %2};" : "=l"(d) : "f"(lo), "f"(hi))
#define UNPACK2(lo, hi, v) \
    asm("mov.b64 {%0, %1}, %2;" : "=f"(lo), "=f"(hi) : "l"(v))

// Hardware tanh: single MUFU.TANH (sm_75+). Atom err ~5e-4; verified
// end-to-end rel_err ~1e-7 through the contracting recurrence (R15).
__device__ __forceinline__ float hw_tanh(float x) {
    float y;
    asm("tanh.approx.f32 %0, %1;" : "=f"(y) : "f"(x));
    return y;
}
__device__ __forceinline__ float hw_sigmoid(float x) {
    return 0.5f * (1.0f + hw_tanh(0.5f * x));
}

// Device scratch (sanctioned: __device__ globals, no allocation)
__device__ float g_X0[VOCAB * H];   // emb @ W_ih0 + b0 per vocab id
__device__ int   g_order[B];        // rows sorted by length, descending

// ---------------------------------------------------------------------------
// Kernel B: block 0 rank-sorts lengths, all blocks compute X0.
// ---------------------------------------------------------------------------
__global__ void __launch_bounds__(256)
x0_kernel(const float* __restrict__ emb,
          const float* __restrict__ W_ih,
          const float* __restrict__ b,
          const int* __restrict__ lengths) {
    __shared__ __align__(16) float embs[H];
    __shared__ float part[2 * H];
    __shared__ int s_len[B];

    int tid   = threadIdx.x;
    int half  = tid >> 7;
    int j     = tid & 127;
    int kbase = half * 64;

    if (blockIdx.x == 0) {
        s_len[tid] = lengths[tid];
        __syncthreads();
        int li = s_len[tid];
        int rank = 0;
        for (int jj = 0; jj < B; jj++) {
            int lj = s_len[jj];
            rank += (lj > li) || (lj == li && jj < tid);
        }
        g_order[rank] = tid;
        __syncthreads();
    }

    ull w[32];
    #pragma unroll
    for (int kk = 0; kk < 32; kk++) {
        int k = kbase + 2 * kk;
        PACK2(w[kk], W_ih[k * H + j], W_ih[(k + 1) * H + j]);
    }
    float b0 = b[j];

    for (int r = blockIdx.x; r < VOCAB; r += gridDim.x) {
        if (tid < H) embs[tid] = emb[r * E + tid];
        __syncthreads();
        ull acc = 0;
        #pragma unroll
        for (int i = 0; i < 16; i++) {
            ulonglong2 ev = *(const ulonglong2*)&embs[kbase + 4 * i];
            FMA2(acc, ev.x, w[2 * i], acc);
            FMA2(acc, ev.y, w[2 * i + 1], acc);
        }
        float lo, hi;
        UNPACK2(lo, hi, acc);
        part[tid] = lo + hi;
        __syncthreads();
        if (tid < H) g_X0[r * H + j] = b0 + part[j] + part[H + j];
        __syncthreads();
    }
}

// ---------------------------------------------------------------------------
// Kernel C: persistent per-row RNN, 384 threads = 12 warps, 3 warps/SMSP.
//   warps 0-3  (h0-warps): thread = col j (0..127), FULL-k W_hh0 . h0(t).
//       -> s is the complete dot product: NO shuffle. Writes h0(t+1).
//   warps 4-11 (h1-warps): col j = 16*(w-4)+(l&15), k-half = (l&31)>>4.
//       merged W_ih1.h0 + W_hh1.h1 partial over the half; one bfly-16;
//       half==0 lanes write h1(t).
// BOTH run the identical 4-chain x 16-FMA2 inner loop (chain lat 64 cyc
// << per-warp issue 128 cyc) over (ptrA, wA) and (ptrB, wB):
//   h0-warp: ptrA=h0[0..63] wA=W_hh0[0:64],  ptrB=h0[64..127] wB=W_hh0[64:128]
//   h1-warp: ptrA=h0[kb..]  wA=W_ih1[half],  ptrB=h1[kb..]    wB=W_hh1[half]
// Weights: 64 ull regs/thread. h double-buffered -> 1 barrier/step.
// ---------------------------------------------------------------------------
__global__ void __launch_bounds__(384, 1)
rnn_kernel(const int* __restrict__ x, const int* __restrict__ lengths,
           const float* __restrict__ W_ih, const float* __restrict__ W_hh,
           const float* __restrict__ b, const float* __restrict__ cls_w,
           const float* __restrict__ cls_b, float* __restrict__ out) {
    __shared__ int xrow[T];
    __shared__ __align__(16) float h0s[2][H];
    __shared__ __align__(16) float h1s[2][H];

    int tid  = threadIdx.x;
    bool is0 = (tid < 128);
    int u    = tid - 128;                       // valid for h1-warps
    int j    = is0 ? tid : ((u >> 5) * 16 + (u & 15));
    int half = is0 ? 0 : ((u & 31) >> 4);

    int kA = is0 ? 0  : half * 64;              // k-range of wA
    int kB = is0 ? 64 : half * 64;              // k-range of wB

    const float* wsrcA = is0 ? W_hh : (W_ih + H * H);   // W_hh0 | W_ih1
    const float* wsrcB = is0 ? W_hh : (W_hh + H * H);   // W_hh0 | W_hh1

    ull wA[32], wB[32];
    #pragma unroll
    for (int kk = 0; kk < 32; kk++) {
        PACK2(wA[kk], wsrcA[(kA + 2 * kk) * H + j], wsrcA[(kA + 2 * kk + 1) * H + j]);
        PACK2(wB[kk], wsrcB[(kB + 2 * kk) * H + j], wsrcB[(kB + 2 * kk + 1) * H + j]);
    }
    float b1v = b[H + j];

    int row = g_order[blockIdx.x];
    int len = lengths[row];

    // Stage token ids (8 KB).
    for (int i = tid; i < T; i += 384) xrow[i] = x[row * T + i];
    __syncthreads();

    // Prologue: h0(0) = tanh(X0[tok0]) (b0 folded, h_init=0); h1(-1) = 0.
    if (is0)            h0s[0][j] = hw_tanh(g_X0[xrow[0] * H + j]);
    else if (half == 0) h1s[0][j] = 0.f;
    float x0cur = 0.f, x0nxt = 0.f;
    if (is0) x0cur = g_X0[xrow[(len > 1) ? 1 : 0] * H + j];
    __syncthreads();

    for (int t = 0; t < len; t++) {
        int p = t & 1;
        const float* ptrA = &h0s[p][kA];
        const float* ptrB = is0 ? &h0s[p][kB] : &h1s[p][kB];

        // h0-warps prefetch X0 for superstep t+1 (tok[t+2]).
        if (is0) {
            int tn = t + 2;
            if (tn > len - 1) tn = len - 1;
            x0nxt = g_X0[xrow[tn] * H + j];
        }

        // Uniform inner loop: 4 chains x 16 FMA2.
        ull a0 = 0, a1 = 0, a2 = 0, a3 = 0;
        #pragma unroll
        for (int i = 0; i < 16; i++) {
            ulonglong2 ha = *(const ulonglong2*)(ptrA + 4 * i);
            FMA2(a0, ha.x, wA[2 * i],     a0);
            FMA2(a1, ha.y, wA[2 * i + 1], a1);
            ulonglong2 hb = *(const ulonglong2*)(ptrB + 4 * i);
            FMA2(a2, hb.x, wB[2 * i],     a2);
            FMA2(a3, hb.y, wB[2 * i + 1], a3);
        }
        float l0, h0v, l1, h1v, l2, h2v, l3, h3v;
        UNPACK2(l0, h0v, a0); UNPACK2(l1, h1v, a1);
        UNPACK2(l2, h2v, a2); UNPACK2(l3, h3v, a3);
        float s = ((l0 + h0v) + (l1 + h1v)) + ((l2 + h2v) + (l3 + h3v));

        if (is0) {
            // Full dot product already complete: no shuffle.
            h0s[p ^ 1][j] = hw_tanh(x0cur + s);
        } else {
            float sr = s + __shfl_xor_sync(0xffffffffu, s, 16);
            if (half == 0) h1s[p ^ 1][j] = hw_tanh(b1v + sr);
        }
        __syncthreads();

        x0cur = x0nxt;
    }

    // ---- classifier: sigmoid(h1_final . cls_w + cls_b) ----
    const float* h1f = h1s[len & 1];
    if (tid < 32) {
        float v = 0.f;
        #pragma unroll
        for (int m = 0; m < 4; m++) {
            int jj = tid + 32 * m;
            v += h1f[jj] * cls_w[jj];
        }
        #pragma unroll
        for (int off = 16; off; off >>= 1)
            v += __shfl_xor_sync(0xffffffffu, v, off);
        if (tid == 0) out[row] = hw_sigmoid(v + cls_b[0]);
    }
}

// ---------------------------------------------------------------------------
extern "C" void kernel_launch(void* const* d_in, const int* in_sizes, int n_in,
                              void* d_out, int out_size) {
    const int*   x       = (const int*)d_in[0];
    const int*   lengths = (const int*)d_in[1];
    const float* emb     = (const float*)d_in[2];
    const float* W_ih    = (const float*)d_in[3];
    const float* W_hh    = (const float*)d_in[4];
    const float* b       = (const float*)d_in[5];
    const float* cls_w   = (const float*)d_in[6];
    const float* cls_b   = (const float*)d_in[7];
    float*       out     = (float*)d_out;

    x0_kernel<<<1024, 256>>>(emb, W_ih, b, lengths);
    rnn_kernel<<<B, 384>>>(x, lengths, W_ih, W_hh, b, cls_w, cls_b, out);
}

// round 17
// speedup vs baseline: 1.1491x; 1.1491x over previous
#include <cuda_runtime.h>
#include <math.h>

#define VOCAB 50000
#define E 128
#define H 128
#define B 256
#define T 2048

typedef unsigned long long ull;

// Packed f32x2 ops (Blackwell)
#define FMA2(d, a, b, c) \
    asm("fma.rn.f32x2 %0, %1, %2, %3;" : "=l"(d) : "l"(a), "l"(b), "l"(c))
#define ADD2(d, a, b) \
    asm("add.rn.f32x2 %0, %1, %2;" : "=l"(d) : "l"(a), "l"(b))
#define PACK2(d, lo, hi) \
    asm("mov.b64 %0, {%1, %2};" : "=l"(d) : "f"(lo), "f"(hi))
#define UNPACK2(lo, hi, v) \
    asm("mov.b64 {%0, %1}, %2;" : "=f"(lo), "=f"(hi) : "l"(v))

// Hardware tanh: single MUFU.TANH (sm_75+). Atom err ~5e-4; verified
// end-to-end rel_err ~1e-7 through the contracting recurrence (R15).
__device__ __forceinline__ float hw_tanh(float x) {
    float y;
    asm("tanh.approx.f32 %0, %1;" : "=f"(y) : "f"(x));
    return y;
}
__device__ __forceinline__ float hw_sigmoid(float x) {
    return 0.5f * (1.0f + hw_tanh(0.5f * x));
}

// Device scratch (sanctioned: __device__ globals, no allocation)
__device__ float g_X0[VOCAB * H];   // emb @ W_ih0 + b0 per vocab id
__device__ int   g_order[B];        // rows sorted by length, descending

// ---------------------------------------------------------------------------
// Kernel B: block 0 rank-sorts lengths, all blocks compute X0.
// ---------------------------------------------------------------------------
__global__ void __launch_bounds__(256)
x0_kernel(const float* __restrict__ emb,
          const float* __restrict__ W_ih,
          const float* __restrict__ b,
          const int* __restrict__ lengths) {
    __shared__ __align__(16) float embs[H];
    __shared__ float part[2 * H];
    __shared__ int s_len[B];

    int tid   = threadIdx.x;
    int half  = tid >> 7;
    int j     = tid & 127;
    int kbase = half * 64;

    if (blockIdx.x == 0) {
        s_len[tid] = lengths[tid];
        __syncthreads();
        int li = s_len[tid];
        int rank = 0;
        for (int jj = 0; jj < B; jj++) {
            int lj = s_len[jj];
            rank += (lj > li) || (lj == li && jj < tid);
        }
        g_order[rank] = tid;
        __syncthreads();
    }

    ull w[32];
    #pragma unroll
    for (int kk = 0; kk < 32; kk++) {
        int k = kbase + 2 * kk;
        PACK2(w[kk], W_ih[k * H + j], W_ih[(k + 1) * H + j]);
    }
    float b0 = b[j];

    for (int r = blockIdx.x; r < VOCAB; r += gridDim.x) {
        if (tid < H) embs[tid] = emb[r * E + tid];
        __syncthreads();
        ull acc = 0;
        #pragma unroll
        for (int i = 0; i < 16; i++) {
            ulonglong2 ev = *(const ulonglong2*)&embs[kbase + 4 * i];
            FMA2(acc, ev.x, w[2 * i], acc);
            FMA2(acc, ev.y, w[2 * i + 1], acc);
        }
        float lo, hi;
        UNPACK2(lo, hi, acc);
        part[tid] = lo + hi;
        __syncthreads();
        if (tid < H) g_X0[r * H + j] = b0 + part[j] + part[H + j];
        __syncthreads();
    }
}

// ---------------------------------------------------------------------------
// Kernel C: persistent per-row RNN (R15 structure; single-shuffle tail).
// 256 CTAs (one sorted row each, longest first), 256 threads = 8 warps.
// Lane layout: warp w, lane l -> column j = 16*w + (l&15), k-half = l>>4.
// Superstep t computes BOTH h1(t) and h0(t+1) from {h0(t), h1(t-1)}:
//   h1(t)   = tanh(b1 + W_ih1 h0(t) + W_hh1 h1(t-1))
//   h0(t+1) = tanh(X0[tok(t+1)] + W_hh0 h0(t))
// Three independent FMA2 chains; acc1+acc2 merged with a packed add.
// Cross-half exchange is ONE bfly-16: each thread sends what its partner
// needs (half0 sends s12, half1 sends s0). 1 barrier/step.
// ---------------------------------------------------------------------------
__global__ void __launch_bounds__(256, 1)
rnn_kernel(const int* __restrict__ x, const int* __restrict__ lengths,
           const float* __restrict__ W_ih, const float* __restrict__ W_hh,
           const float* __restrict__ b, const float* __restrict__ cls_w,
           const float* __restrict__ cls_b, float* __restrict__ out) {
    __shared__ int xrow[T];
    __shared__ __align__(16) float h0s[2][H];
    __shared__ __align__(16) float h1s[2][H];

    int tid   = threadIdx.x;
    int warp  = tid >> 5;
    int lane  = tid & 31;
    int j     = warp * 16 + (lane & 15);
    int half  = lane >> 4;
    int kbase = half * 64;

    int row = g_order[blockIdx.x];
    int len = lengths[row];

    // Pre-packed weight k-pair columns in registers: 3 x 32 ull.
    ull w0p[32], w1p[32], w2p[32];
    #pragma unroll
    for (int kk = 0; kk < 32; kk++) {
        int k = kbase + 2 * kk;
        PACK2(w0p[kk], W_hh[k * H + j],           W_hh[(k + 1) * H + j]);           // W_hh0
        PACK2(w1p[kk], W_ih[H * H + k * H + j],   W_ih[H * H + (k + 1) * H + j]);   // W_ih1
        PACK2(w2p[kk], W_hh[H * H + k * H + j],   W_hh[H * H + (k + 1) * H + j]);   // W_hh1
    }
    float b1v = b[H + j];

    // Stage token ids for this row into smem (8 KB).
    for (int i = tid; i < T; i += 256) xrow[i] = x[row * T + i];
    __syncthreads();

    // Prologue: h0(0) = tanh(X0[tok0]) (b0 folded into X0, h_init = 0); h1(-1)=0.
    if (half == 0) h0s[0][j] = hw_tanh(g_X0[xrow[0] * H + j]);
    else           h1s[0][j] = 0.f;
    float x0cur = 0.f, x0nxt = 0.f;
    if (half == 0) x0cur = g_X0[xrow[(len > 1) ? 1 : 0] * H + j];
    __syncthreads();

    #pragma unroll 2
    for (int t = 0; t < len; t++) {
        int p = t & 1;
        const float* hr0 = &h0s[p][kbase];
        const float* hr1 = &h1s[p][kbase];

        // Prefetch X0 for superstep t+1 (needs tok[t+2]).
        if (half == 0) {
            int tn = t + 2;
            if (tn > len - 1) tn = len - 1;
            x0nxt = g_X0[xrow[tn] * H + j];
        }

        // Three matmul partials over this k-half (FFMA2-packed, 3 chains).
        ull acc0 = 0, acc1 = 0, acc2 = 0;
        #pragma unroll
        for (int i = 0; i < 16; i++) {
            ulonglong2 hp = *(const ulonglong2*)(hr0 + 4 * i);
            FMA2(acc0, hp.x, w0p[2 * i],     acc0);
            FMA2(acc0, hp.y, w0p[2 * i + 1], acc0);
            FMA2(acc1, hp.x, w1p[2 * i],     acc1);
            FMA2(acc1, hp.y, w1p[2 * i + 1], acc1);
            ulonglong2 gp = *(const ulonglong2*)(hr1 + 4 * i);
            FMA2(acc2, gp.x, w2p[2 * i],     acc2);
            FMA2(acc2, gp.y, w2p[2 * i + 1], acc2);
        }

        // Collapse: s0 from acc0; s12 from packed acc1+acc2 (one unpack).
        ull acc12;
        ADD2(acc12, acc1, acc2);
        float lo, hi, s0, s12;
        UNPACK2(lo, hi, acc0);  s0  = lo + hi;
        UNPACK2(lo, hi, acc12); s12 = lo + hi;

        // ONE cross-half exchange: send what the partner needs.
        // half0's partner (half1) needs s12; half1's partner needs s0.
        float sel  = half ? s0 : s12;
        float recv = __shfl_xor_sync(0xffffffffu, sel, 16);
        // half0: argv = x0 + s0_own + s0_partner(recv)
        // half1: argv = b1 + s12_own + s12_partner(recv)
        float argv = (half ? (b1v + s12) : (x0cur + s0)) + recv;
        float hv = hw_tanh(argv);

        // Double-buffered write: no WAR hazard, single barrier per step.
        float* dst = half ? &h1s[p ^ 1][0] : &h0s[p ^ 1][0];
        dst[j] = hv;
        __syncthreads();

        x0cur = x0nxt;
    }

    // ---- classifier: sigmoid(h1_final . cls_w + cls_b) ----
    const float* h1f = h1s[len & 1];
    if (tid < 32) {
        float v = 0.f;
        #pragma unroll
        for (int m = 0; m < 4; m++) {
            int jj = tid + 32 * m;
            v += h1f[jj] * cls_w[jj];
        }
        #pragma unroll
        for (int off = 16; off; off >>= 1)
            v += __shfl_xor_sync(0xffffffffu, v, off);
        if (tid == 0) out[row] = hw_sigmoid(v + cls_b[0]);
    }
}

// ---------------------------------------------------------------------------
extern "C" void kernel_launch(void* const* d_in, const int* in_sizes, int n_in,
                              void* d_out, int out_size) {
    const int*   x       = (const int*)d_in[0];
    const int*   lengths = (const int*)d_in[1];
    const float* emb     = (const float*)d_in[2];
    const float* W_ih    = (const float*)d_in[3];
    const float* W_hh    = (const float*)d_in[4];
    const float* b       = (const float*)d_in[5];
    const float* cls_w   = (const float*)d_in[6];
    const float* cls_b   = (const float*)d_in[7];
    float*       out     = (float*)d_out;

    x0_kernel<<<1024, 256>>>(emb, W_ih, b, lengths);
    rnn_kernel<<<B, 256>>>(x, lengths, W_ih, W_hh, b, cls_w, cls_b, out);
}